// round 9
// baseline (speedup 1.0000x reference)
#include <cuda_runtime.h>
#include <cstdint>

#define M_GT  512
#define N_CTX 1024
#define FEAT  1024
#define NG    16
#define DK    64
#define MN    (M_GT * N_CTX)   // 524288

// ---------------- device scratch (static globals; no allocation) ------------
__device__ float g_Q [M_GT * FEAT];
__device__ float g_K [N_CTX * FEAT];
__device__ float g_Ut[FEAT * M_GT];    // Ut[o][m]
__device__ float g_Vt[FEAT * N_CTX];   // Vt[o][n]
__device__ float g_S [NG * MN];        // scores  (G, M, N)
__device__ float g_St[NG * MN];        // scores^T (G, N, M)
__device__ float g_L1[NG * MN];        // weights gt  (G, M, N)
__device__ float g_L2[NG * MN];        // weights ctx (G, N, M)

// 1000^(-j/8)
__constant__ float c_invdim[8] = {
    1.0f, 0.4216965034f, 0.1778279410f, 0.0749894209f,
    0.0316227766f, 0.0133352143f, 0.0056234133f, 0.0023713737f
};

// ---------------- stream orchestration (created at static-init time) --------
struct Orch {
    cudaStream_t s2;
    cudaEvent_t evRoot, evScores, evPos2, evUtVt;
    Orch() {
        cudaStreamCreateWithFlags(&s2, cudaStreamNonBlocking);
        cudaEventCreateWithFlags(&evRoot,   cudaEventDisableTiming);
        cudaEventCreateWithFlags(&evScores, cudaEventDisableTiming);
        cudaEventCreateWithFlags(&evPos2,   cudaEventDisableTiming);
        cudaEventCreateWithFlags(&evUtVt,   cudaEventDisableTiming);
    }
};
static Orch g_orch;

// ======================= helpers ==========================
__device__ __forceinline__ uint32_t f2tf(float x) {
    uint32_t r;
    asm("cvt.rna.tf32.f32 %0, %1;" : "=r"(r) : "f"(x));
    return r;
}

__device__ __forceinline__ void mma8(float* c, const uint32_t* a, const uint32_t* b) {
    asm volatile(
        "mma.sync.aligned.m16n8k8.row.col.f32.tf32.tf32.f32 "
        "{%0,%1,%2,%3}, {%4,%5,%6,%7}, {%8,%9}, {%0,%1,%2,%3};"
        : "+f"(c[0]), "+f"(c[1]), "+f"(c[2]), "+f"(c[3])
        : "r"(a[0]), "r"(a[1]), "r"(a[2]), "r"(a[3]), "r"(b[0]), "r"(b[1]));
}

__device__ __forceinline__ void cp16(uint32_t s, const void* g) {
    asm volatile("cp.async.cg.shared.global [%0], [%1], 16;" :: "r"(s), "l"(g));
}
#define CP_COMMIT() asm volatile("cp.async.commit_group;" ::: "memory")
#define CP_WAIT1()  asm volatile("cp.async.wait_group 1;" ::: "memory")
#define CP_WAIT0()  asm volatile("cp.async.wait_group 0;" ::: "memory")

#define LDP 36   // smem row pitch (floats)

template <int ROWS>
__device__ __forceinline__ void issue_chunk(const float* __restrict__ g, int ld,
                                            uint32_t smbase, int tid)
{
#pragma unroll
    for (int i = 0; i < ROWS / 32; i++) {
        int idx = tid + i * 256;
        int r = idx >> 3, c = (idx & 7) << 2;
        cp16(smbase + (uint32_t)(r * LDP + c) * 4u, g + (size_t)r * ld + c);
    }
}

template <int ROWS>
__device__ __forceinline__ void stage(const float* __restrict__ g, int ld,
                                      uint32_t* __restrict__ sm, int tid)
{
#pragma unroll
    for (int i = 0; i < ROWS / 32; i++) {
        int idx = tid + i * 256;
        int r = idx >> 3, c = (idx & 7) << 2;
        float4 v = *(const float4*)(g + (size_t)r * ld + c);
        uint4 t;
        t.x = f2tf(v.x); t.y = f2tf(v.y); t.z = f2tf(v.z); t.w = f2tf(v.w);
        *(uint4*)(sm + r * LDP + c) = t;
    }
}

// ---------------------------------------------------------------------------
// proj_mma: C = A @ W^T (+bias along N). 128x128 tiles, K=1024.
// zbase splits the 4 cases into independent launches.
// ---------------------------------------------------------------------------
#define PROJ_BUF (128 * LDP * 2)

__global__ __launch_bounds__(256, 2) void proj_mma(
    const float* __restrict__ feat, const float* __restrict__ ctx_feat,
    const float* __restrict__ w_gt, const float* __restrict__ b_gt,
    const float* __restrict__ w_ctx, const float* __restrict__ b_ctx,
    const float* __restrict__ w_conv, int zbase)
{
    const float* A; const float* W; const float* bias; float* C;
    int Mrows, Ncols;
    switch (blockIdx.z + zbase) {
    case 0:  A = feat;   W = w_gt;     bias = b_gt;  C = g_Q;  Mrows = M_GT;  Ncols = FEAT;  break;
    case 1:  A = ctx_feat; W = w_ctx;  bias = b_ctx; C = g_K;  Mrows = N_CTX; Ncols = FEAT;  break;
    case 2:  A = w_conv; W = feat;     bias = 0;     C = g_Ut; Mrows = FEAT;  Ncols = M_GT;  break;
    default: A = w_conv; W = ctx_feat; bias = 0;     C = g_Vt; Mrows = FEAT;  Ncols = N_CTX; break;
    }
    int bm = blockIdx.y * 128, bn = blockIdx.x * 128;
    if (bm >= Mrows || bn >= Ncols) return;

    extern __shared__ float dsm[];
    uint32_t smb = (uint32_t)__cvta_generic_to_shared(dsm);

    int tid = threadIdx.x, wid = tid >> 5, lane = tid & 31;
    int g4 = lane >> 2, tig = lane & 3;
    int wm = (wid & 1) * 64, wn = (wid >> 1) * 32;

    float acc[4][4][4];
#pragma unroll
    for (int i = 0; i < 4; i++)
#pragma unroll
        for (int j = 0; j < 4; j++)
#pragma unroll
            for (int q = 0; q < 4; q++) acc[i][j][q] = 0.0f;

    const float* Ab = A + (size_t)bm * FEAT;
    const float* Wb = W + (size_t)bn * FEAT;

    issue_chunk<128>(Ab, FEAT, smb, tid);
    issue_chunk<128>(Wb, FEAT, smb + 128 * LDP * 4u, tid);
    CP_COMMIT();

    const int NCH = FEAT / 32;
    for (int ch = 0; ch < NCH; ch++) {
        int buf = ch & 1;
        if (ch + 1 < NCH) {
            uint32_t nb = smb + (uint32_t)((ch + 1) & 1) * PROJ_BUF * 4u;
            issue_chunk<128>(Ab + (ch + 1) * 32, FEAT, nb, tid);
            issue_chunk<128>(Wb + (ch + 1) * 32, FEAT, nb + 128 * LDP * 4u, tid);
            CP_COMMIT();
            CP_WAIT1();
        } else {
            CP_WAIT0();
        }
        __syncthreads();
        const float* As = dsm + buf * PROJ_BUF;
        const float* Bs = As + 128 * LDP;
#pragma unroll
        for (int kk = 0; kk < 4; kk++) {
            int k0 = kk * 8 + tig;
            uint32_t bf[4][2];
#pragma unroll
            for (int j = 0; j < 4; j++) {
                int rn = (wn + j * 8 + g4) * LDP;
                bf[j][0] = f2tf(Bs[rn + k0]);
                bf[j][1] = f2tf(Bs[rn + k0 + 4]);
            }
#pragma unroll
            for (int i = 0; i < 4; i++) {
                int r0 = (wm + i * 16 + g4) * LDP;
                uint32_t af[4];
                af[0] = f2tf(As[r0 + k0]);
                af[1] = f2tf(As[r0 + 8 * LDP + k0]);
                af[2] = f2tf(As[r0 + k0 + 4]);
                af[3] = f2tf(As[r0 + 8 * LDP + k0 + 4]);
#pragma unroll
                for (int j = 0; j < 4; j++) mma8(acc[i][j], af, bf[j]);
            }
        }
        __syncthreads();
    }

#pragma unroll
    for (int i = 0; i < 4; i++) {
        int row = bm + wm + i * 16 + g4;
#pragma unroll
        for (int j = 0; j < 4; j++) {
            int col = bn + wn + j * 8 + 2 * tig;
            float b0 = bias ? bias[col] : 0.0f;
            float b1 = bias ? bias[col + 1] : 0.0f;
            float2 o0, o1;
            o0.x = acc[i][j][0] + b0; o0.y = acc[i][j][1] + b1;
            o1.x = acc[i][j][2] + b0; o1.y = acc[i][j][3] + b1;
            *(float2*)(C + (size_t)row * Ncols + col)       = o0;
            *(float2*)(C + (size_t)(row + 8) * Ncols + col) = o1;
        }
    }
}

// ---------------------------------------------------------------------------
// scores_mma: S[g,m,n] = 0.125 * Q.K ; St[g,n,m] via smem transpose.
// ---------------------------------------------------------------------------
#define TP 68

__global__ __launch_bounds__(256, 2) void scores_mma()
{
    int g = blockIdx.z;
    int bm = blockIdx.y * 128, bn = blockIdx.x * 128;
    const float* A = g_Q + (size_t)bm * FEAT + g * DK;
    const float* B = g_K + (size_t)bn * FEAT + g * DK;
    float* C  = g_S  + (size_t)g * MN;
    float* Ct = g_St + (size_t)g * MN;

    __shared__ __align__(16) uint32_t sbuf[2 * 128 * LDP];
    uint32_t* As = sbuf;
    uint32_t* Bs = sbuf + 128 * LDP;
    float* T = (float*)sbuf;

    int tid = threadIdx.x, wid = tid >> 5, lane = tid & 31;
    int g4 = lane >> 2, tig = lane & 3;
    int wm = (wid & 1) * 64, wn = (wid >> 1) * 32;

    float acc[4][4][4];
#pragma unroll
    for (int i = 0; i < 4; i++)
#pragma unroll
        for (int j = 0; j < 4; j++)
#pragma unroll
            for (int q = 0; q < 4; q++) acc[i][j][q] = 0.0f;

    for (int ch = 0; ch < 2; ch++) {
        stage<128>(A + ch * 32, FEAT, As, tid);
        stage<128>(B + ch * 32, FEAT, Bs, tid);
        __syncthreads();
#pragma unroll
        for (int kk = 0; kk < 4; kk++) {
            int k0 = kk * 8 + tig;
            uint32_t bf[4][2];
#pragma unroll
            for (int j = 0; j < 4; j++) {
                int rn = (wn + j * 8 + g4) * LDP;
                bf[j][0] = Bs[rn + k0];
                bf[j][1] = Bs[rn + k0 + 4];
            }
#pragma unroll
            for (int i = 0; i < 4; i++) {
                int r0 = (wm + i * 16 + g4) * LDP;
                uint32_t af[4];
                af[0] = As[r0 + k0];
                af[1] = As[r0 + 8 * LDP + k0];
                af[2] = As[r0 + k0 + 4];
                af[3] = As[r0 + 8 * LDP + k0 + 4];
#pragma unroll
                for (int j = 0; j < 4; j++) mma8(acc[i][j], af, bf[j]);
            }
        }
        __syncthreads();
    }

#pragma unroll
    for (int i = 0; i < 4; i++) {
        int row = bm + wm + i * 16 + g4;
#pragma unroll
        for (int j = 0; j < 4; j++) {
            int col = bn + wn + j * 8 + 2 * tig;
            float2 o0, o1;
            o0.x = acc[i][j][0] * 0.125f; o0.y = acc[i][j][1] * 0.125f;
            o1.x = acc[i][j][2] * 0.125f; o1.y = acc[i][j][3] * 0.125f;
            *(float2*)(C + (size_t)row * N_CTX + col)       = o0;
            *(float2*)(C + (size_t)(row + 8) * N_CTX + col) = o1;
        }
    }

    for (int hh = 0; hh < 2; hh++) {
        __syncthreads();
        if ((wid & 1) == hh) {
#pragma unroll
            for (int i = 0; i < 4; i++) {
                int rl = i * 16 + g4;
#pragma unroll
                for (int j = 0; j < 4; j++) {
                    int col = wn + j * 8 + 2 * tig;
                    T[col * TP + rl]            = acc[i][j][0] * 0.125f;
                    T[(col + 1) * TP + rl]      = acc[i][j][1] * 0.125f;
                    T[col * TP + rl + 8]        = acc[i][j][2] * 0.125f;
                    T[(col + 1) * TP + rl + 8]  = acc[i][j][3] * 0.125f;
                }
            }
        }
        __syncthreads();
        int col = tid >> 1, seg = (tid & 1) << 5;
        const float* src = T + col * TP + seg;
        float* dst = Ct + (size_t)(bn + col) * M_GT + bm + hh * 64 + seg;
#pragma unroll
        for (int k = 0; k < 8; k++)
            *(float4*)(dst + k * 4) = *(const float4*)(src + k * 4);
    }
}

// ---------------------------------------------------------------------------
// attn_mma: z 0..15 gt, z 16..31 ctx. 128x64 tiles, warp tile 64x16.
// ---------------------------------------------------------------------------
#define ATTN_BUF (128 * LDP + 64 * LDP)

__global__ __launch_bounds__(256, 2) void attn_mma(
    const float* __restrict__ b_conv, float* __restrict__ out_gt,
    float* __restrict__ out_ctx)
{
    int z = blockIdx.z;
    int g = z & 15;
    bool gt = z < 16;
    const float* A = gt ? g_L1 + (size_t)g * MN : g_L2 + (size_t)g * MN;
    const float* B = gt ? g_Vt + (size_t)(g * DK) * N_CTX
                        : g_Ut + (size_t)(g * DK) * M_GT;
    float* C  = gt ? out_gt : out_ctx;
    int Mrows = gt ? M_GT : N_CTX;
    int Ktot  = gt ? N_CTX : M_GT;
    int bm = blockIdx.y * 128;
    if (bm >= Mrows) return;

    extern __shared__ float dsm[];
    uint32_t smb = (uint32_t)__cvta_generic_to_shared(dsm);

    int tid = threadIdx.x, wid = tid >> 5, lane = tid & 31;
    int g4 = lane >> 2, tig = lane & 3;
    int wm = (wid & 1) * 64, wn = (wid >> 1) * 16;

    float acc[4][2][4];
#pragma unroll
    for (int i = 0; i < 4; i++)
#pragma unroll
        for (int j = 0; j < 2; j++)
#pragma unroll
            for (int q = 0; q < 4; q++) acc[i][j][q] = 0.0f;

    const float* Ab = A + (size_t)bm * Ktot;

    issue_chunk<128>(Ab, Ktot, smb, tid);
    issue_chunk<64>(B, Ktot, smb + 128 * LDP * 4u, tid);
    CP_COMMIT();

    int NCH = Ktot / 32;
    for (int ch = 0; ch < NCH; ch++) {
        int buf = ch & 1;
        if (ch + 1 < NCH) {
            uint32_t nb = smb + (uint32_t)((ch + 1) & 1) * ATTN_BUF * 4u;
            issue_chunk<128>(Ab + (ch + 1) * 32, Ktot, nb, tid);
            issue_chunk<64>(B + (ch + 1) * 32, Ktot, nb + 128 * LDP * 4u, tid);
            CP_COMMIT();
            CP_WAIT1();
        } else {
            CP_WAIT0();
        }
        __syncthreads();
        const float* As = dsm + buf * ATTN_BUF;
        const float* Bs = As + 128 * LDP;
#pragma unroll
        for (int kk = 0; kk < 4; kk++) {
            int k0 = kk * 8 + tig;
            uint32_t bf[2][2];
#pragma unroll
            for (int j = 0; j < 2; j++) {
                int rn = (wn + j * 8 + g4) * LDP;
                bf[j][0] = f2tf(Bs[rn + k0]);
                bf[j][1] = f2tf(Bs[rn + k0 + 4]);
            }
#pragma unroll
            for (int i = 0; i < 4; i++) {
                int r0 = (wm + i * 16 + g4) * LDP;
                uint32_t af[4];
                af[0] = f2tf(As[r0 + k0]);
                af[1] = f2tf(As[r0 + 8 * LDP + k0]);
                af[2] = f2tf(As[r0 + k0 + 4]);
                af[3] = f2tf(As[r0 + 8 * LDP + k0 + 4]);
#pragma unroll
                for (int j = 0; j < 2; j++) mma8(acc[i][j], af, bf[j]);
            }
        }
        __syncthreads();
    }

#pragma unroll
    for (int i = 0; i < 4; i++) {
        int row = bm + wm + i * 16 + g4;
#pragma unroll
        for (int j = 0; j < 2; j++) {
            int col = g * DK + wn + j * 8 + 2 * tig;
            float b0 = b_conv[col], b1 = b_conv[col + 1];
            float2 o0, o1;
            o0.x = acc[i][j][0] + b0; o0.y = acc[i][j][1] + b1;
            o1.x = acc[i][j][2] + b0; o1.y = acc[i][j][3] + b1;
            *(float2*)(C + (size_t)row * FEAT + col)       = o0;
            *(float2*)(C + (size_t)(row + 8) * FEAT + col) = o1;
        }
    }
}

// ---------------------------------------------------------------------------
// pos_soft<NCOLS>: fused pos-embedding + logit + row softmax.
// ---------------------------------------------------------------------------
template <int NCOLS>
__global__ __launch_bounds__(NCOLS / 4, 512 / (NCOLS / 4)) void pos_soft(
    const float4* __restrict__ boxA, const float4* __restrict__ boxB,
    const float* __restrict__ w_pos, const float* __restrict__ b_pos,
    const float* __restrict__ Sb, float* __restrict__ L)
{
    constexpr int NT = NCOLS / 4;
    constexpr int NW = NT / 32;
    extern __shared__ float sl[];
    __shared__ __align__(16) float wq[512 * 4];
    __shared__ float bp[NG];
    __shared__ float rbuf[NG * (NW + 1)];

    int tid = threadIdx.x, wid = tid >> 5, lane = tid & 31;
    for (int i = tid; i < 512; i += NT) {
        int pj = i >> 4, g = i & 15;
        int p = pj >> 3, j = pj & 7;
        float ws = w_pos[g * 64 + p * 16 + j];
        float wc = w_pos[g * 64 + p * 16 + 8 + j];
        wq[i * 4 + 0] = ws; wq[i * 4 + 1] = ws;
        wq[i * 4 + 2] = wc; wq[i * 4 + 3] = wc;
    }
    if (tid < NG) bp[tid] = b_pos[tid];
    __syncthreads();

    int r = blockIdx.x;
    int c0 = tid * 4;

    float4 A = boxA[r];
    float bw = A.z - A.x + 1.0f, bh = A.w - A.y + 1.0f;
    float cx = 0.5f * (A.x + A.z), cy = 0.5f * (A.y + A.w);

    float pp[4][4];
#pragma unroll
    for (int q = 0; q < 4; q++) {
        float4 Bx = boxB[c0 + q];
        pp[q][0] = __logf(fmaxf(fabsf((cx - 0.5f * (Bx.x + Bx.z)) / bw), 1e-3f));
        pp[q][1] = __logf(fmaxf(fabsf((cy - 0.5f * (Bx.y + Bx.w)) / bh), 1e-3f));
        pp[q][2] = __logf((Bx.z - Bx.x + 1.0f) / bw);
        pp[q][3] = __logf((Bx.w - Bx.y + 1.0f) / bh);
    }

    unsigned long long acc[NG][2];
#pragma unroll
    for (int g = 0; g < NG; g++) { acc[g][0] = 0ull; acc[g][1] = 0ull; }

    const ulonglong2* wq2 = (const ulonglong2*)wq;
#pragma unroll
    for (int p = 0; p < 4; p++) {
        float b0 = 100.0f * pp[0][p], b1 = 100.0f * pp[1][p];
        float b2 = 100.0f * pp[2][p], b3 = 100.0f * pp[3][p];
#pragma unroll
        for (int j = 0; j < 8; j++) {
            float iv = c_invdim[j];
            float s0, v0, s1, v1, s2, v2, s3, v3;
            __sincosf(b0 * iv, &s0, &v0);
            __sincosf(b1 * iv, &s1, &v1);
            __sincosf(b2 * iv, &s2, &v2);
            __sincosf(b3 * iv, &s3, &v3);
            s0 = fmaxf(s0, 0.0f); s1 = fmaxf(s1, 0.0f);
            s2 = fmaxf(s2, 0.0f); s3 = fmaxf(s3, 0.0f);
            v0 = fmaxf(v0, 0.0f); v1 = fmaxf(v1, 0.0f);
            v2 = fmaxf(v2, 0.0f); v3 = fmaxf(v3, 0.0f);
            unsigned long long ss01, ss23, cc01, cc23;
            asm("mov.b64 %0, {%1, %2};" : "=l"(ss01) : "f"(s0), "f"(s1));
            asm("mov.b64 %0, {%1, %2};" : "=l"(ss23) : "f"(s2), "f"(s3));
            asm("mov.b64 %0, {%1, %2};" : "=l"(cc01) : "f"(v0), "f"(v1));
            asm("mov.b64 %0, {%1, %2};" : "=l"(cc23) : "f"(v2), "f"(v3));
            int e = (p * 8 + j) * 16;
#pragma unroll
            for (int g = 0; g < NG; g++) {
                ulonglong2 w = wq2[e + g];
                asm("fma.rn.f32x2 %0, %1, %2, %0;" : "+l"(acc[g][0]) : "l"(ss01), "l"(w.x));
                asm("fma.rn.f32x2 %0, %1, %2, %0;" : "+l"(acc[g][1]) : "l"(ss23), "l"(w.x));
                asm("fma.rn.f32x2 %0, %1, %2, %0;" : "+l"(acc[g][0]) : "l"(cc01), "l"(w.y));
                asm("fma.rn.f32x2 %0, %1, %2, %0;" : "+l"(acc[g][1]) : "l"(cc23), "l"(w.y));
            }
        }
    }

    float mx[NG];
#pragma unroll
    for (int g = 0; g < NG; g++) {
        float a0, a1, a2, a3;
        asm("mov.b64 {%0, %1}, %2;" : "=f"(a0), "=f"(a1) : "l"(acc[g][0]));
        asm("mov.b64 {%0, %1}, %2;" : "=f"(a2), "=f"(a3) : "l"(acc[g][1]));
        float4 sc = *(const float4*)(Sb + (size_t)g * MN + (size_t)r * NCOLS + c0);
        float bg = bp[g];
        float4 o;
        o.x = __logf(fmaxf(a0 + bg, 1e-6f)) + sc.x;
        o.y = __logf(fmaxf(a1 + bg, 1e-6f)) + sc.y;
        o.z = __logf(fmaxf(a2 + bg, 1e-6f)) + sc.z;
        o.w = __logf(fmaxf(a3 + bg, 1e-6f)) + sc.w;
        *(float4*)&sl[g * NCOLS + c0] = o;
        mx[g] = fmaxf(fmaxf(o.x, o.y), fmaxf(o.z, o.w));
    }

#pragma unroll
    for (int g = 0; g < NG; g++) {
#pragma unroll
        for (int o = 16; o; o >>= 1)
            mx[g] = fmaxf(mx[g], __shfl_xor_sync(0xffffffffu, mx[g], o));
    }
    if (lane == 0) {
#pragma unroll
        for (int g = 0; g < NG; g++) rbuf[g * (NW + 1) + wid] = mx[g];
    }
    __syncthreads();
    if (tid < NG) {
        float t = rbuf[tid * (NW + 1)];
#pragma unroll
        for (int w = 1; w < NW; w++) t = fmaxf(t, rbuf[tid * (NW + 1) + w]);
        rbuf[tid * (NW + 1) + NW] = t;
    }
    __syncthreads();

    float sum[NG];
#pragma unroll
    for (int g = 0; g < NG; g++) {
        float m = rbuf[g * (NW + 1) + NW];
        float4 v = *(float4*)&sl[g * NCOLS + c0];
        v.x = __expf(v.x - m); v.y = __expf(v.y - m);
        v.z = __expf(v.z - m); v.w = __expf(v.w - m);
        *(float4*)&sl[g * NCOLS + c0] = v;
        sum[g] = (v.x + v.y) + (v.z + v.w);
    }
    __syncthreads();
#pragma unroll
    for (int g = 0; g < NG; g++) {
#pragma unroll
        for (int o = 16; o; o >>= 1)
            sum[g] += __shfl_xor_sync(0xffffffffu, sum[g], o);
    }
    if (lane == 0) {
#pragma unroll
        for (int g = 0; g < NG; g++) rbuf[g * (NW + 1) + wid] = sum[g];
    }
    __syncthreads();
    if (tid < NG) {
        float t = 0.0f;
#pragma unroll
        for (int w = 0; w < NW; w++) t += rbuf[tid * (NW + 1) + w];
        rbuf[tid * (NW + 1) + NW] = t;
    }
    __syncthreads();

#pragma unroll
    for (int g = 0; g < NG; g++) {
        float inv = __frcp_rn(rbuf[g * (NW + 1) + NW]);
        float4 v = *(float4*)&sl[g * NCOLS + c0];
        v.x *= inv; v.y *= inv; v.z *= inv; v.w *= inv;
        *(float4*)(L + (size_t)g * MN + (size_t)r * NCOLS + c0) = v;
    }
}

// ---------------------------------------------------------------------------
extern "C" void kernel_launch(void* const* d_in, const int* in_sizes, int n_in,
                              void* d_out, int out_size)
{
    (void)in_sizes; (void)n_in; (void)out_size;
    const float* feat      = (const float*)d_in[0];
    const float* ctx_feat  = (const float*)d_in[1];
    const float* box       = (const float*)d_in[2];
    const float* ctx_box   = (const float*)d_in[3];
    const float* w_fc_gt   = (const float*)d_in[4];
    const float* b_fc_gt   = (const float*)d_in[5];
    const float* w_fc_ctx  = (const float*)d_in[6];
    const float* b_fc_ctx  = (const float*)d_in[7];
    const float* w_pos_gt  = (const float*)d_in[8];
    const float* b_pos_gt  = (const float*)d_in[9];
    const float* w_pos_ctx = (const float*)d_in[10];
    const float* b_pos_ctx = (const float*)d_in[11];
    const float* w_conv    = (const float*)d_in[12];
    const float* b_conv    = (const float*)d_in[13];

    float* out = (float*)d_out;
    float* out_gt  = out;
    float* out_ctx = out + (size_t)M_GT * FEAT;

    float *S, *St, *L1, *L2;
    cudaGetSymbolAddress((void**)&S,  g_S);
    cudaGetSymbolAddress((void**)&St, g_St);
    cudaGetSymbolAddress((void**)&L1, g_L1);
    cudaGetSymbolAddress((void**)&L2, g_L2);

    static int attr_done = 0;
    if (!attr_done) {
        cudaFuncSetAttribute(proj_mma, cudaFuncAttributeMaxDynamicSharedMemorySize,
                             2 * PROJ_BUF * 4);
        cudaFuncSetAttribute(attn_mma, cudaFuncAttributeMaxDynamicSharedMemorySize,
                             2 * ATTN_BUF * 4);
        cudaFuncSetAttribute(pos_soft<N_CTX>, cudaFuncAttributeMaxDynamicSharedMemorySize,
                             NG * N_CTX * 4);
        cudaFuncSetAttribute(pos_soft<M_GT>, cudaFuncAttributeMaxDynamicSharedMemorySize,
                             NG * M_GT * 4);
        attr_done = 1;
    }

    cudaStream_t s2 = g_orch.s2;

    // fork: root event so stream-2 work joins the capture DAG
    cudaEventRecord(g_orch.evRoot, 0);
    cudaStreamWaitEvent(s2, g_orch.evRoot, 0);

    // s2: Ut/Vt projection (independent of everything until attn)
    proj_mma<<<dim3(8, 8, 2), 256, 2 * PROJ_BUF * 4, s2>>>(
        feat, ctx_feat, w_fc_gt, b_fc_gt, w_fc_ctx, b_fc_ctx, w_conv, 2);
    cudaEventRecord(g_orch.evUtVt, s2);

    // main: Q,K projection then scores
    proj_mma<<<dim3(8, 8, 2), 256, 2 * PROJ_BUF * 4>>>(
        feat, ctx_feat, w_fc_gt, b_fc_gt, w_fc_ctx, b_fc_ctx, w_conv, 0);
    scores_mma<<<dim3(8, 4, 16), 256>>>();
    cudaEventRecord(g_orch.evScores, 0);

    // s2: pos dir-2 (needs scores^T)
    cudaStreamWaitEvent(s2, g_orch.evScores, 0);
    pos_soft<M_GT><<<N_CTX, M_GT / 4, NG * M_GT * 4, s2>>>(
        (const float4*)ctx_box, (const float4*)box, w_pos_ctx, b_pos_ctx, St, L2);
    cudaEventRecord(g_orch.evPos2, s2);

    // main: pos dir-1 (needs scores)
    pos_soft<N_CTX><<<M_GT, N_CTX / 4, NG * N_CTX * 4>>>(
        (const float4*)box, (const float4*)ctx_box, w_pos_gt, b_pos_gt, S, L1);

    // join: attn needs pos1, pos2, Ut/Vt
    cudaStreamWaitEvent(0, g_orch.evPos2, 0);
    cudaStreamWaitEvent(0, g_orch.evUtVt, 0);
    attn_mma<<<dim3(1, 8, 32), 256, 2 * ATTN_BUF * 4>>>(b_conv, out_gt, out_ctx);
}

// round 10
// speedup vs baseline: 1.0392x; 1.0392x over previous
#include <cuda_runtime.h>
#include <cstdint>

#define M_GT  512
#define N_CTX 1024
#define FEAT  1024
#define NG    16
#define DK    64
#define MN    (M_GT * N_CTX)   // 524288

// ---------------- device scratch (static globals; no allocation) ------------
__device__ float g_Q [M_GT * FEAT];
__device__ float g_K [N_CTX * FEAT];
__device__ float g_Ut[FEAT * M_GT];    // Ut[o][m]
__device__ float g_Vt[FEAT * N_CTX];   // Vt[o][n]
__device__ float g_S [NG * MN];        // scores  (G, M, N)
__device__ float g_St[NG * MN];        // scores^T (G, N, M)
__device__ float g_L1[NG * MN];        // weights gt  (G, M, N)
__device__ float g_L2[NG * MN];        // weights ctx (G, N, M)
__device__ float g_tabA[M_GT * 36];    // per-box sin/cos tables (gt boxes)
__device__ float g_tabB[N_CTX * 36];   // per-box sin/cos tables (ctx boxes)

// 1000^(-j/8)
__constant__ float c_invdim[8] = {
    1.0f, 0.4216965034f, 0.1778279410f, 0.0749894209f,
    0.0316227766f, 0.0133352143f, 0.0056234133f, 0.0023713737f
};

// ======================= helpers ==========================
__device__ __forceinline__ uint32_t f2tf(float x) {
    uint32_t r;
    asm("cvt.rna.tf32.f32 %0, %1;" : "=r"(r) : "f"(x));
    return r;
}

__device__ __forceinline__ void mma8(float* c, const uint32_t* a, const uint32_t* b) {
    asm volatile(
        "mma.sync.aligned.m16n8k8.row.col.f32.tf32.tf32.f32 "
        "{%0,%1,%2,%3}, {%4,%5,%6,%7}, {%8,%9}, {%0,%1,%2,%3};"
        : "+f"(c[0]), "+f"(c[1]), "+f"(c[2]), "+f"(c[3])
        : "r"(a[0]), "r"(a[1]), "r"(a[2]), "r"(a[3]), "r"(b[0]), "r"(b[1]));
}

__device__ __forceinline__ void cp16(uint32_t s, const void* g) {
    asm volatile("cp.async.cg.shared.global [%0], [%1], 16;" :: "r"(s), "l"(g));
}
#define CP_COMMIT() asm volatile("cp.async.commit_group;" ::: "memory")
#define CP_WAIT1()  asm volatile("cp.async.wait_group 1;" ::: "memory")
#define CP_WAIT0()  asm volatile("cp.async.wait_group 0;" ::: "memory")

#define LDP 36   // smem row pitch (floats)

template <int ROWS>
__device__ __forceinline__ void issue_chunk(const float* __restrict__ g, int ld,
                                            uint32_t smbase, int tid)
{
#pragma unroll
    for (int i = 0; i < ROWS / 32; i++) {
        int idx = tid + i * 256;
        int r = idx >> 3, c = (idx & 7) << 2;
        cp16(smbase + (uint32_t)(r * LDP + c) * 4u, g + (size_t)r * ld + c);
    }
}

template <int ROWS>
__device__ __forceinline__ void stage(const float* __restrict__ g, int ld,
                                      uint32_t* __restrict__ sm, int tid)
{
#pragma unroll
    for (int i = 0; i < ROWS / 32; i++) {
        int idx = tid + i * 256;
        int r = idx >> 3, c = (idx & 7) << 2;
        float4 v = *(const float4*)(g + (size_t)r * ld + c);
        uint4 t;
        t.x = f2tf(v.x); t.y = f2tf(v.y); t.z = f2tf(v.z); t.w = f2tf(v.w);
        *(uint4*)(sm + r * LDP + c) = t;
    }
}

// ---------------------------------------------------------------------------
// boxtab_k: per-box sin/cos tables for the separable dw/dh embedding dims.
// tab[box][0..15]  = (sin, cos) of 100*log(w)*invdim[j], j=0..7
// tab[box][16..31] = same for h. (angles pre-scaled by 100)
// ---------------------------------------------------------------------------
__global__ void boxtab_k(const float4* __restrict__ box,
                         const float4* __restrict__ ctx_box)
{
    int i = blockIdx.x * 128 + threadIdx.x;
    float4 Bx; float* dst;
    if (i < M_GT) { Bx = box[i]; dst = g_tabA + (size_t)i * 36; }
    else if (i < M_GT + N_CTX) { Bx = ctx_box[i - M_GT]; dst = g_tabB + (size_t)(i - M_GT) * 36; }
    else return;
    float lw = 100.0f * __logf(Bx.z - Bx.x + 1.0f);
    float lh = 100.0f * __logf(Bx.w - Bx.y + 1.0f);
#pragma unroll
    for (int j = 0; j < 8; j++) {
        float s, c;
        __sincosf(lw * c_invdim[j], &s, &c);
        dst[2 * j] = s; dst[2 * j + 1] = c;
        __sincosf(lh * c_invdim[j], &s, &c);
        dst[16 + 2 * j] = s; dst[17 + 2 * j] = c;
    }
}

// ---------------------------------------------------------------------------
// proj_mma: C = A @ W^T (+bias along N). 128x128 tiles, K=1024.
// ---------------------------------------------------------------------------
#define PROJ_BUF (128 * LDP * 2)

__global__ __launch_bounds__(256, 2) void proj_mma(
    const float* __restrict__ feat, const float* __restrict__ ctx_feat,
    const float* __restrict__ w_gt, const float* __restrict__ b_gt,
    const float* __restrict__ w_ctx, const float* __restrict__ b_ctx,
    const float* __restrict__ w_conv)
{
    const float* A; const float* W; const float* bias; float* C;
    int Mrows, Ncols;
    switch (blockIdx.z) {
    case 0:  A = feat;   W = w_gt;     bias = b_gt;  C = g_Q;  Mrows = M_GT;  Ncols = FEAT;  break;
    case 1:  A = ctx_feat; W = w_ctx;  bias = b_ctx; C = g_K;  Mrows = N_CTX; Ncols = FEAT;  break;
    case 2:  A = w_conv; W = feat;     bias = 0;     C = g_Ut; Mrows = FEAT;  Ncols = M_GT;  break;
    default: A = w_conv; W = ctx_feat; bias = 0;     C = g_Vt; Mrows = FEAT;  Ncols = N_CTX; break;
    }
    int bm = blockIdx.y * 128, bn = blockIdx.x * 128;
    if (bm >= Mrows || bn >= Ncols) return;

    extern __shared__ float dsm[];
    uint32_t smb = (uint32_t)__cvta_generic_to_shared(dsm);

    int tid = threadIdx.x, wid = tid >> 5, lane = tid & 31;
    int g4 = lane >> 2, tig = lane & 3;
    int wm = (wid & 1) * 64, wn = (wid >> 1) * 32;

    float acc[4][4][4];
#pragma unroll
    for (int i = 0; i < 4; i++)
#pragma unroll
        for (int j = 0; j < 4; j++)
#pragma unroll
            for (int q = 0; q < 4; q++) acc[i][j][q] = 0.0f;

    const float* Ab = A + (size_t)bm * FEAT;
    const float* Wb = W + (size_t)bn * FEAT;

    issue_chunk<128>(Ab, FEAT, smb, tid);
    issue_chunk<128>(Wb, FEAT, smb + 128 * LDP * 4u, tid);
    CP_COMMIT();

    const int NCH = FEAT / 32;
    for (int ch = 0; ch < NCH; ch++) {
        int buf = ch & 1;
        if (ch + 1 < NCH) {
            uint32_t nb = smb + (uint32_t)((ch + 1) & 1) * PROJ_BUF * 4u;
            issue_chunk<128>(Ab + (ch + 1) * 32, FEAT, nb, tid);
            issue_chunk<128>(Wb + (ch + 1) * 32, FEAT, nb + 128 * LDP * 4u, tid);
            CP_COMMIT();
            CP_WAIT1();
        } else {
            CP_WAIT0();
        }
        __syncthreads();
        const float* As = dsm + buf * PROJ_BUF;
        const float* Bs = As + 128 * LDP;
#pragma unroll
        for (int kk = 0; kk < 4; kk++) {
            int k0 = kk * 8 + tig;
            uint32_t bf[4][2];
#pragma unroll
            for (int j = 0; j < 4; j++) {
                int rn = (wn + j * 8 + g4) * LDP;
                bf[j][0] = f2tf(Bs[rn + k0]);
                bf[j][1] = f2tf(Bs[rn + k0 + 4]);
            }
#pragma unroll
            for (int i = 0; i < 4; i++) {
                int r0 = (wm + i * 16 + g4) * LDP;
                uint32_t af[4];
                af[0] = f2tf(As[r0 + k0]);
                af[1] = f2tf(As[r0 + 8 * LDP + k0]);
                af[2] = f2tf(As[r0 + k0 + 4]);
                af[3] = f2tf(As[r0 + 8 * LDP + k0 + 4]);
#pragma unroll
                for (int j = 0; j < 4; j++) mma8(acc[i][j], af, bf[j]);
            }
        }
        __syncthreads();
    }

#pragma unroll
    for (int i = 0; i < 4; i++) {
        int row = bm + wm + i * 16 + g4;
#pragma unroll
        for (int j = 0; j < 4; j++) {
            int col = bn + wn + j * 8 + 2 * tig;
            float b0 = bias ? bias[col] : 0.0f;
            float b1 = bias ? bias[col + 1] : 0.0f;
            float2 o0, o1;
            o0.x = acc[i][j][0] + b0; o0.y = acc[i][j][1] + b1;
            o1.x = acc[i][j][2] + b0; o1.y = acc[i][j][3] + b1;
            *(float2*)(C + (size_t)row * Ncols + col)       = o0;
            *(float2*)(C + (size_t)(row + 8) * Ncols + col) = o1;
        }
    }
}

// ---------------------------------------------------------------------------
// scores_mma: S[g,m,n] = 0.125 * Q.K ; St[g,n,m] via smem transpose.
// ---------------------------------------------------------------------------
#define TP 68

__global__ __launch_bounds__(256, 2) void scores_mma()
{
    int g = blockIdx.z;
    int bm = blockIdx.y * 128, bn = blockIdx.x * 128;
    const float* A = g_Q + (size_t)bm * FEAT + g * DK;
    const float* B = g_K + (size_t)bn * FEAT + g * DK;
    float* C  = g_S  + (size_t)g * MN;
    float* Ct = g_St + (size_t)g * MN;

    __shared__ __align__(16) uint32_t sbuf[2 * 128 * LDP];
    uint32_t* As = sbuf;
    uint32_t* Bs = sbuf + 128 * LDP;
    float* T = (float*)sbuf;

    int tid = threadIdx.x, wid = tid >> 5, lane = tid & 31;
    int g4 = lane >> 2, tig = lane & 3;
    int wm = (wid & 1) * 64, wn = (wid >> 1) * 32;

    float acc[4][4][4];
#pragma unroll
    for (int i = 0; i < 4; i++)
#pragma unroll
        for (int j = 0; j < 4; j++)
#pragma unroll
            for (int q = 0; q < 4; q++) acc[i][j][q] = 0.0f;

    for (int ch = 0; ch < 2; ch++) {
        stage<128>(A + ch * 32, FEAT, As, tid);
        stage<128>(B + ch * 32, FEAT, Bs, tid);
        __syncthreads();
#pragma unroll
        for (int kk = 0; kk < 4; kk++) {
            int k0 = kk * 8 + tig;
            uint32_t bf[4][2];
#pragma unroll
            for (int j = 0; j < 4; j++) {
                int rn = (wn + j * 8 + g4) * LDP;
                bf[j][0] = Bs[rn + k0];
                bf[j][1] = Bs[rn + k0 + 4];
            }
#pragma unroll
            for (int i = 0; i < 4; i++) {
                int r0 = (wm + i * 16 + g4) * LDP;
                uint32_t af[4];
                af[0] = As[r0 + k0];
                af[1] = As[r0 + 8 * LDP + k0];
                af[2] = As[r0 + k0 + 4];
                af[3] = As[r0 + 8 * LDP + k0 + 4];
#pragma unroll
                for (int j = 0; j < 4; j++) mma8(acc[i][j], af, bf[j]);
            }
        }
        __syncthreads();
    }

#pragma unroll
    for (int i = 0; i < 4; i++) {
        int row = bm + wm + i * 16 + g4;
#pragma unroll
        for (int j = 0; j < 4; j++) {
            int col = bn + wn + j * 8 + 2 * tig;
            float2 o0, o1;
            o0.x = acc[i][j][0] * 0.125f; o0.y = acc[i][j][1] * 0.125f;
            o1.x = acc[i][j][2] * 0.125f; o1.y = acc[i][j][3] * 0.125f;
            *(float2*)(C + (size_t)row * N_CTX + col)       = o0;
            *(float2*)(C + (size_t)(row + 8) * N_CTX + col) = o1;
        }
    }

    for (int hh = 0; hh < 2; hh++) {
        __syncthreads();
        if ((wid & 1) == hh) {
#pragma unroll
            for (int i = 0; i < 4; i++) {
                int rl = i * 16 + g4;
#pragma unroll
                for (int j = 0; j < 4; j++) {
                    int col = wn + j * 8 + 2 * tig;
                    T[col * TP + rl]            = acc[i][j][0] * 0.125f;
                    T[(col + 1) * TP + rl]      = acc[i][j][1] * 0.125f;
                    T[col * TP + rl + 8]        = acc[i][j][2] * 0.125f;
                    T[(col + 1) * TP + rl + 8]  = acc[i][j][3] * 0.125f;
                }
            }
        }
        __syncthreads();
        int col = tid >> 1, seg = (tid & 1) << 5;
        const float* src = T + col * TP + seg;
        float* dst = Ct + (size_t)(bn + col) * M_GT + bm + hh * 64 + seg;
#pragma unroll
        for (int k = 0; k < 8; k++)
            *(float4*)(dst + k * 4) = *(const float4*)(src + k * 4);
    }
}

// ---------------------------------------------------------------------------
// attn_mma: z 0..15 gt, z 16..31 ctx. 128x64 tiles, warp tile 64x16.
// ---------------------------------------------------------------------------
#define ATTN_BUF (128 * LDP + 64 * LDP)

__global__ __launch_bounds__(256, 2) void attn_mma(
    const float* __restrict__ b_conv, float* __restrict__ out_gt,
    float* __restrict__ out_ctx)
{
    int z = blockIdx.z;
    int g = z & 15;
    bool gt = z < 16;
    const float* A = gt ? g_L1 + (size_t)g * MN : g_L2 + (size_t)g * MN;
    const float* B = gt ? g_Vt + (size_t)(g * DK) * N_CTX
                        : g_Ut + (size_t)(g * DK) * M_GT;
    float* C  = gt ? out_gt : out_ctx;
    int Mrows = gt ? M_GT : N_CTX;
    int Ktot  = gt ? N_CTX : M_GT;
    int bm = blockIdx.y * 128;
    if (bm >= Mrows) return;

    extern __shared__ float dsm[];
    uint32_t smb = (uint32_t)__cvta_generic_to_shared(dsm);

    int tid = threadIdx.x, wid = tid >> 5, lane = tid & 31;
    int g4 = lane >> 2, tig = lane & 3;
    int wm = (wid & 1) * 64, wn = (wid >> 1) * 16;

    float acc[4][2][4];
#pragma unroll
    for (int i = 0; i < 4; i++)
#pragma unroll
        for (int j = 0; j < 2; j++)
#pragma unroll
            for (int q = 0; q < 4; q++) acc[i][j][q] = 0.0f;

    const float* Ab = A + (size_t)bm * Ktot;

    issue_chunk<128>(Ab, Ktot, smb, tid);
    issue_chunk<64>(B, Ktot, smb + 128 * LDP * 4u, tid);
    CP_COMMIT();

    int NCH = Ktot / 32;
    for (int ch = 0; ch < NCH; ch++) {
        int buf = ch & 1;
        if (ch + 1 < NCH) {
            uint32_t nb = smb + (uint32_t)((ch + 1) & 1) * ATTN_BUF * 4u;
            issue_chunk<128>(Ab + (ch + 1) * 32, Ktot, nb, tid);
            issue_chunk<64>(B + (ch + 1) * 32, Ktot, nb + 128 * LDP * 4u, tid);
            CP_COMMIT();
            CP_WAIT1();
        } else {
            CP_WAIT0();
        }
        __syncthreads();
        const float* As = dsm + buf * ATTN_BUF;
        const float* Bs = As + 128 * LDP;
#pragma unroll
        for (int kk = 0; kk < 4; kk++) {
            int k0 = kk * 8 + tig;
            uint32_t bf[2][2];
#pragma unroll
            for (int j = 0; j < 2; j++) {
                int rn = (wn + j * 8 + g4) * LDP;
                bf[j][0] = f2tf(Bs[rn + k0]);
                bf[j][1] = f2tf(Bs[rn + k0 + 4]);
            }
#pragma unroll
            for (int i = 0; i < 4; i++) {
                int r0 = (wm + i * 16 + g4) * LDP;
                uint32_t af[4];
                af[0] = f2tf(As[r0 + k0]);
                af[1] = f2tf(As[r0 + 8 * LDP + k0]);
                af[2] = f2tf(As[r0 + k0 + 4]);
                af[3] = f2tf(As[r0 + 8 * LDP + k0 + 4]);
#pragma unroll
                for (int j = 0; j < 2; j++) mma8(acc[i][j], af, bf[j]);
            }
        }
        __syncthreads();
    }

#pragma unroll
    for (int i = 0; i < 4; i++) {
        int row = bm + wm + i * 16 + g4;
#pragma unroll
        for (int j = 0; j < 2; j++) {
            int col = g * DK + wn + j * 8 + 2 * tig;
            float b0 = b_conv[col], b1 = b_conv[col + 1];
            float2 o0, o1;
            o0.x = acc[i][j][0] + b0; o0.y = acc[i][j][1] + b1;
            o1.x = acc[i][j][2] + b0; o1.y = acc[i][j][3] + b1;
            *(float2*)(C + (size_t)row * FEAT + col)       = o0;
            *(float2*)(C + (size_t)(row + 8) * FEAT + col) = o1;
        }
    }
}

// ---------------------------------------------------------------------------
// pos_soft<NCOLS>: fused pos-embedding + logit + row softmax, TENSOR-CORE
// pos-linear. One block per row. Each warp covers 128 columns as 8 m16 tiles.
// Lane (g4,tig) computes pe for cols {g4, g4+8} of the tile, feats f==tig mod 4
// -> exactly the m16n8k8 A-fragment layout; no smem staging of pe.
// Bias GEMM uses 3-term tf32 hi/lo split for fp32-like accuracy.
// dw/dh embedding dims come from per-box tables via angle-difference identity.
// ---------------------------------------------------------------------------
template <int NCOLS>
__global__ __launch_bounds__(NCOLS / 4, 512 / (NCOLS / 4)) void pos_soft(
    const float4* __restrict__ boxA, const float4* __restrict__ boxB,
    const float* __restrict__ tabA, const float* __restrict__ tabB,
    const float* __restrict__ w_pos, const float* __restrict__ b_pos,
    const float* __restrict__ Sb, float* __restrict__ L)
{
    constexpr int NT = NCOLS / 4;
    constexpr int NW = NT / 32;
    constexpr int SLP = NCOLS + 4;            // smem logits pitch (conflict-free)
    extern __shared__ float sl[];             // [NG][SLP]
    __shared__ float wbh[16 * 68];            // w_pos tf32-hi, pitch 68
    __shared__ float wbl[16 * 68];            // w_pos tf32-lo
    __shared__ float bp[NG];
    __shared__ float rbuf[NG * (NW + 1)];

    int tid = threadIdx.x, wid = tid >> 5, lane = tid & 31;
    int g4 = lane >> 2, tig = lane & 3;

    for (int i = tid; i < 1024; i += NT) {
        int g = i >> 6, f = i & 63;
        float w = w_pos[i];
        uint32_t hb = f2tf(w);
        float hf = __uint_as_float(hb);
        wbh[g * 68 + f] = hf;
        wbl[g * 68 + f] = __uint_as_float(f2tf(w - hf));
    }
    if (tid < NG) bp[tid] = b_pos[tid];
    __syncthreads();

    int r = blockIdx.x;
    float4 A = boxA[r];
    float bw = A.z - A.x + 1.0f, bh = A.w - A.y + 1.0f;
    float cx = 0.5f * (A.x + A.z), cy = 0.5f * (A.y + A.w);
    float rbw = 1.0f / bw, rbh = 1.0f / bh;
    float ivA = c_invdim[tig], ivB = c_invdim[tig + 4];

    // row-side table values for this thread's j lanes (sin, cos)
    const float* tr = tabA + (size_t)r * 36;
    float2 rw0 = *(const float2*)(tr + 2 * tig);
    float2 rw1 = *(const float2*)(tr + 2 * tig + 8);
    float2 rh0 = *(const float2*)(tr + 16 + 2 * tig);
    float2 rh1 = *(const float2*)(tr + 24 + 2 * tig);

    for (int mt = 0; mt < 8; mt++) {
        int base = wid * 128 + mt * 16;
        float a[2][8][2];   // [col ci][kk][k-half]
#pragma unroll
        for (int ci = 0; ci < 2; ci++) {
            int col = base + ci * 8 + g4;
            float4 Bx = boxB[col];
            float p0 = 100.0f * __logf(fmaxf(fabsf((cx - 0.5f * (Bx.x + Bx.z)) * rbw), 1e-3f));
            float p1 = 100.0f * __logf(fmaxf(fabsf((cy - 0.5f * (Bx.y + Bx.w)) * rbh), 1e-3f));
            float s, c;
            __sincosf(p0 * ivA, &s, &c);
            a[ci][0][0] = fmaxf(s, 0.0f); a[ci][1][0] = fmaxf(c, 0.0f);
            __sincosf(p0 * ivB, &s, &c);
            a[ci][0][1] = fmaxf(s, 0.0f); a[ci][1][1] = fmaxf(c, 0.0f);
            __sincosf(p1 * ivA, &s, &c);
            a[ci][2][0] = fmaxf(s, 0.0f); a[ci][3][0] = fmaxf(c, 0.0f);
            __sincosf(p1 * ivB, &s, &c);
            a[ci][2][1] = fmaxf(s, 0.0f); a[ci][3][1] = fmaxf(c, 0.0f);
            // dw, dh via angle difference: sin(tc-tr), cos(tc-tr)
            const float* tc = tabB + (size_t)col * 36;
            float2 cw0 = *(const float2*)(tc + 2 * tig);
            float2 cw1 = *(const float2*)(tc + 2 * tig + 8);
            float2 ch0 = *(const float2*)(tc + 16 + 2 * tig);
            float2 ch1 = *(const float2*)(tc + 24 + 2 * tig);
            a[ci][4][0] = fmaxf(cw0.x * rw0.y - cw0.y * rw0.x, 0.0f);
            a[ci][4][1] = fmaxf(cw1.x * rw1.y - cw1.y * rw1.x, 0.0f);
            a[ci][5][0] = fmaxf(cw0.y * rw0.y + cw0.x * rw0.x, 0.0f);
            a[ci][5][1] = fmaxf(cw1.y * rw1.y + cw1.x * rw1.x, 0.0f);
            a[ci][6][0] = fmaxf(ch0.x * rh0.y - ch0.y * rh0.x, 0.0f);
            a[ci][6][1] = fmaxf(ch1.x * rh1.y - ch1.y * rh1.x, 0.0f);
            a[ci][7][0] = fmaxf(ch0.y * rh0.y + ch0.x * rh0.x, 0.0f);
            a[ci][7][1] = fmaxf(ch1.y * rh1.y + ch1.x * rh1.x, 0.0f);
        }

        float acc[2][4];
#pragma unroll
        for (int j = 0; j < 2; j++)
#pragma unroll
            for (int q = 0; q < 4; q++) acc[j][q] = 0.0f;

#pragma unroll
        for (int kk = 0; kk < 8; kk++) {
            uint32_t ah[4], al[4];
#pragma unroll
            for (int q = 0; q < 4; q++) {
                float v = a[q & 1][kk][q >> 1];
                uint32_t h = f2tf(v);
                ah[q] = h;
                al[q] = f2tf(v - __uint_as_float(h));
            }
            int ko = 8 * kk + tig;
#pragma unroll
            for (int j = 0; j < 2; j++) {
                int rb = (8 * j + g4) * 68 + ko;
                uint32_t bh2[2], bl2[2];
                bh2[0] = __float_as_uint(wbh[rb]);
                bh2[1] = __float_as_uint(wbh[rb + 4]);
                bl2[0] = __float_as_uint(wbl[rb]);
                bl2[1] = __float_as_uint(wbl[rb + 4]);
                mma8(acc[j], ah, bh2);
                mma8(acc[j], ah, bl2);
                mma8(acc[j], al, bh2);
            }
        }

        // logits for this tile: cols (cA, cB) x groups (ga, gb) per j
        int cA = base + g4, cB = cA + 8;
        size_t sro = (size_t)r * NCOLS;
#pragma unroll
        for (int j = 0; j < 2; j++) {
            int ga = 8 * j + 2 * tig, gb = ga + 1;
            float l0 = __logf(fmaxf(acc[j][0] + bp[ga], 1e-6f)) + Sb[(size_t)ga * MN + sro + cA];
            float l1 = __logf(fmaxf(acc[j][1] + bp[gb], 1e-6f)) + Sb[(size_t)gb * MN + sro + cA];
            float l2 = __logf(fmaxf(acc[j][2] + bp[ga], 1e-6f)) + Sb[(size_t)ga * MN + sro + cB];
            float l3 = __logf(fmaxf(acc[j][3] + bp[gb], 1e-6f)) + Sb[(size_t)gb * MN + sro + cB];
            sl[ga * SLP + cA] = l0;
            sl[gb * SLP + cA] = l1;
            sl[ga * SLP + cB] = l2;
            sl[gb * SLP + cB] = l3;
        }
    }
    __syncthreads();

    // ---- phase 2: row softmax over sl (per group) ----
    int c0 = tid * 4;
    float mx[NG];
#pragma unroll
    for (int g = 0; g < NG; g++) {
        float4 v = *(float4*)&sl[g * SLP + c0];
        mx[g] = fmaxf(fmaxf(v.x, v.y), fmaxf(v.z, v.w));
    }
#pragma unroll
    for (int g = 0; g < NG; g++) {
#pragma unroll
        for (int o = 16; o; o >>= 1)
            mx[g] = fmaxf(mx[g], __shfl_xor_sync(0xffffffffu, mx[g], o));
    }
    if (lane == 0) {
#pragma unroll
        for (int g = 0; g < NG; g++) rbuf[g * (NW + 1) + wid] = mx[g];
    }
    __syncthreads();
    if (tid < NG) {
        float t = rbuf[tid * (NW + 1)];
#pragma unroll
        for (int w = 1; w < NW; w++) t = fmaxf(t, rbuf[tid * (NW + 1) + w]);
        rbuf[tid * (NW + 1) + NW] = t;
    }
    __syncthreads();

    float sum[NG];
#pragma unroll
    for (int g = 0; g < NG; g++) {
        float m = rbuf[g * (NW + 1) + NW];
        float4 v = *(float4*)&sl[g * SLP + c0];
        v.x = __expf(v.x - m); v.y = __expf(v.y - m);
        v.z = __expf(v.z - m); v.w = __expf(v.w - m);
        *(float4*)&sl[g * SLP + c0] = v;
        sum[g] = (v.x + v.y) + (v.z + v.w);
    }
    __syncthreads();
#pragma unroll
    for (int g = 0; g < NG; g++) {
#pragma unroll
        for (int o = 16; o; o >>= 1)
            sum[g] += __shfl_xor_sync(0xffffffffu, sum[g], o);
    }
    if (lane == 0) {
#pragma unroll
        for (int g = 0; g < NG; g++) rbuf[g * (NW + 1) + wid] = sum[g];
    }
    __syncthreads();
    if (tid < NG) {
        float t = 0.0f;
#pragma unroll
        for (int w = 0; w < NW; w++) t += rbuf[tid * (NW + 1) + w];
        rbuf[tid * (NW + 1) + NW] = t;
    }
    __syncthreads();

#pragma unroll
    for (int g = 0; g < NG; g++) {
        float inv = __frcp_rn(rbuf[g * (NW + 1) + NW]);
        float4 v = *(float4*)&sl[g * SLP + c0];
        v.x *= inv; v.y *= inv; v.z *= inv; v.w *= inv;
        *(float4*)(L + (size_t)g * MN + (size_t)r * NCOLS + c0) = v;
    }
}

// ---------------------------------------------------------------------------
extern "C" void kernel_launch(void* const* d_in, const int* in_sizes, int n_in,
                              void* d_out, int out_size)
{
    (void)in_sizes; (void)n_in; (void)out_size;
    const float* feat      = (const float*)d_in[0];
    const float* ctx_feat  = (const float*)d_in[1];
    const float* box       = (const float*)d_in[2];
    const float* ctx_box   = (const float*)d_in[3];
    const float* w_fc_gt   = (const float*)d_in[4];
    const float* b_fc_gt   = (const float*)d_in[5];
    const float* w_fc_ctx  = (const float*)d_in[6];
    const float* b_fc_ctx  = (const float*)d_in[7];
    const float* w_pos_gt  = (const float*)d_in[8];
    const float* b_pos_gt  = (const float*)d_in[9];
    const float* w_pos_ctx = (const float*)d_in[10];
    const float* b_pos_ctx = (const float*)d_in[11];
    const float* w_conv    = (const float*)d_in[12];
    const float* b_conv    = (const float*)d_in[13];

    float* out = (float*)d_out;
    float* out_gt  = out;
    float* out_ctx = out + (size_t)M_GT * FEAT;

    float *S, *St, *L1, *L2, *tabA, *tabB;
    cudaGetSymbolAddress((void**)&S,    g_S);
    cudaGetSymbolAddress((void**)&St,   g_St);
    cudaGetSymbolAddress((void**)&L1,   g_L1);
    cudaGetSymbolAddress((void**)&L2,   g_L2);
    cudaGetSymbolAddress((void**)&tabA, g_tabA);
    cudaGetSymbolAddress((void**)&tabB, g_tabB);

    static int attr_done = 0;
    if (!attr_done) {
        cudaFuncSetAttribute(proj_mma, cudaFuncAttributeMaxDynamicSharedMemorySize,
                             2 * PROJ_BUF * 4);
        cudaFuncSetAttribute(attn_mma, cudaFuncAttributeMaxDynamicSharedMemorySize,
                             2 * ATTN_BUF * 4);
        cudaFuncSetAttribute(pos_soft<N_CTX>, cudaFuncAttributeMaxDynamicSharedMemorySize,
                             NG * (N_CTX + 4) * 4);
        cudaFuncSetAttribute(pos_soft<M_GT>, cudaFuncAttributeMaxDynamicSharedMemorySize,
                             NG * (M_GT + 4) * 4);
        attr_done = 1;
    }

    // 0) per-box sin/cos tables
    boxtab_k<<<(M_GT + N_CTX + 127) / 128, 128>>>((const float4*)box,
                                                  (const float4*)ctx_box);
    // 1) Q, K, Ut, Vt projections (tf32 mma.sync, cp.async pipelined)
    proj_mma<<<dim3(8, 8, 4), 256, 2 * PROJ_BUF * 4>>>(
        feat, ctx_feat, w_fc_gt, b_fc_gt, w_fc_ctx, b_fc_ctx, w_conv);
    // 2) scores S + St
    scores_mma<<<dim3(8, 4, 16), 256>>>();
    // 3) fused pos-embedding + logits + softmax (tensor-core pos-linear)
    pos_soft<N_CTX><<<M_GT, N_CTX / 4, NG * (N_CTX + 4) * 4>>>(
        (const float4*)box, (const float4*)ctx_box, tabA, tabB,
        w_pos_gt, b_pos_gt, S, L1);
    pos_soft<M_GT><<<N_CTX, M_GT / 4, NG * (M_GT + 4) * 4>>>(
        (const float4*)ctx_box, (const float4*)box, tabB, tabA,
        w_pos_ctx, b_pos_ctx, St, L2);
    // 4) attention output (tf32 mma.sync)
    attn_mma<<<dim3(1, 8, 32), 256, 2 * ATTN_BUF * 4>>>(b_conv, out_gt, out_ctx);
}